// round 15
// baseline (speedup 1.0000x reference)
#include <cuda_runtime.h>
#include <cuda_fp16.h>
#include <math.h>
#include <cstdint>

#define HID 512
#define NMAX 60000
#define EMAX 400000
#define BGRAPH 64
#define NCLS 1000
#define EPSBN 1e-5f
#define LBLK 3
#define INDIM 256

// ---------------- device scratch (fp16 activations, fp32 stats) ----------------
__device__ __half g_h[(size_t)NMAX * HID];
__device__ __half g_aggr[(size_t)NMAX * HID];
__device__ __half g_t[(size_t)NMAX * HID];
__device__ __half g_u[(size_t)NMAX * HID];
__device__ __half g_xh[(size_t)NMAX * INDIM];
__device__ int    g_deg[NMAX];
__device__ int    g_rowptr[NMAX + 1];
__device__ int    g_cursor[NMAX];
__device__ int    g_csr[EMAX];
__device__ float  g_stats[2 * HID];
__device__ float  g_rowss[NMAX];
__device__ float  g_pool[BGRAPH * HID];
__device__ int    g_gcnt[BGRAPH];
__device__ __half g_w1t[(size_t)LBLK * HID * 2 * HID];   // [L][512][1024] (N,K) half
__device__ __half g_w2t[(size_t)LBLK * HID * 2 * HID];
__device__ __half g_wet[(size_t)HID * INDIM];            // [512][256]

// ---------------- helpers ----------------
__device__ __forceinline__ uint32_t smem_u32(const void* p) {
    uint32_t a;
    asm("{ .reg .u64 t; cvta.to.shared.u64 t, %1; cvt.u32.u64 %0, t; }" : "=r"(a) : "l"(p));
    return a;
}
__device__ __forceinline__ void cp_async16(uint32_t saddr, const void* g) {
    asm volatile("cp.async.cg.shared.global [%0], [%1], 16;"
                 :: "r"(saddr), "l"(__cvta_generic_to_global((void*)g)) : "memory");
}
__device__ __forceinline__ void red_add_v4(float4* addr, float4 v) {
    asm volatile("red.global.add.v4.f32 [%0], {%1,%2,%3,%4};"
                 :: "l"(addr), "f"(v.x), "f"(v.y), "f"(v.z), "f"(v.w) : "memory");
}
__device__ __forceinline__ void mma_f16(float* c, const uint32_t* a, const uint32_t* b) {
    asm volatile(
        "mma.sync.aligned.m16n8k16.row.col.f32.f16.f16.f32 "
        "{%0,%1,%2,%3}, {%4,%5,%6,%7}, {%8,%9}, {%0,%1,%2,%3};"
        : "+f"(c[0]), "+f"(c[1]), "+f"(c[2]), "+f"(c[3])
        : "r"(a[0]), "r"(a[1]), "r"(a[2]), "r"(a[3]), "r"(b[0]), "r"(b[1]));
}
#define LDSM4(r0, r1, r2, r3, addr) \
    asm volatile("ldmatrix.sync.aligned.m8n8.x4.shared.b16 {%0,%1,%2,%3}, [%4];" \
                 : "=r"(r0), "=r"(r1), "=r"(r2), "=r"(r3) : "r"(addr))

// ---------------- fp16 tensor-core GEMM: C[M,512] = [A1|A2] @ Bt^T + bias ----------------
// Tile 128x128x64. smem rows = 32 uint32 (64 halves), stride 36 uint32 ->
// ldmatrix phases hit banks 0-31 exactly once (row step = 4 banks). 73728B smem -> 2 CTA/SM.
// NORM: accumulate per-row sum-of-squares of (acc+bias) into rowss (for fused L2 norm).
#define BM 128
#define BN 128
#define BKC 64
#define ASTRIDE 36
#define ASZ (128 * ASTRIDE)                 // uint32 per buffer
#define GEMM_SMEM (4 * ASZ * 4)             // bytes = 73728

template <bool NORM>
__global__ __launch_bounds__(256) void gemm_h_k(
    const __half* __restrict__ A1, int K1,
    const __half* __restrict__ A2, int K2,
    const __half* __restrict__ Bt,
    const float* __restrict__ bias,
    __half* __restrict__ C, float* __restrict__ rowss, int M)
{
    extern __shared__ uint32_t sm[];
    const int tid = threadIdx.x;
    const int wid = tid >> 5, lane = tid & 31;
    const int g = lane >> 2, t = lane & 3;
    const int warp_m = wid & 3, warp_n = wid >> 2;
    const int K = K1 + K2;
    const int nchunk = K / BKC;
    const int rowBase = blockIdx.y * BM;
    const int colBase = blockIdx.x * BN;

    // ldmatrix per-lane source offsets (uint32 units within a buffer)
    const int quad = lane >> 3, qi = lane & 7;
    const int a_row_l = ((quad & 1) << 3) + qi;   // lanes: m-row within 16
    const int a_col16 = quad >> 1;                // k 16B-unit (0: k0-7, 1: k8-15)
    const int b_row_l = ((quad >> 1) << 3) + qi;  // n-row within 16
    const int b_col16 = quad & 1;

    float acc[2][8][4];
#pragma unroll
    for (int mt = 0; mt < 2; mt++)
#pragma unroll
        for (int nt = 0; nt < 8; nt++)
#pragma unroll
            for (int q = 0; q < 4; q++) acc[mt][nt][q] = 0.f;

    auto load_chunk = [&](int ci, int b) {
        uint32_t* ab = sm + b * ASZ;
        uint32_t* bb = sm + 2 * ASZ + b * ASZ;
        const int k0 = ci * BKC;
#pragma unroll
        for (int j = 0; j < 4; j++) {
            int u = tid * 4 + j;
            int r = u >> 3, q = u & 7;
            uint32_t sa = smem_u32(ab + r * ASTRIDE + q * 4);
            int rg = rowBase + r;
            if (rg < M) {
                const __half* gp = (k0 < K1) ? (A1 + (size_t)rg * K1 + k0 + q * 8)
                                             : (A2 + (size_t)rg * K2 + (k0 - K1) + q * 8);
                cp_async16(sa, gp);
            } else {
                asm volatile("st.shared.v4.b32 [%0], {%1,%1,%1,%1};" :: "r"(sa), "r"(0) : "memory");
            }
        }
#pragma unroll
        for (int j = 0; j < 4; j++) {
            int u = tid * 4 + j;
            int r = u >> 3, q = u & 7;
            uint32_t sa = smem_u32(bb + r * ASTRIDE + q * 4);
            cp_async16(sa, Bt + (size_t)(colBase + r) * K + k0 + q * 8);
        }
        asm volatile("cp.async.commit_group;" ::: "memory");
    };

    load_chunk(0, 0);

    for (int ci = 0; ci < nchunk; ci++) {
        const int b = ci & 1;
        if (ci + 1 < nchunk) {
            load_chunk(ci + 1, b ^ 1);
            asm volatile("cp.async.wait_group 1;" ::: "memory");
        } else {
            asm volatile("cp.async.wait_group 0;" ::: "memory");
        }
        __syncthreads();

        uint32_t* ab = sm + b * ASZ;
        uint32_t* bb = sm + 2 * ASZ + b * ASZ;
        // per-buffer ldmatrix base addresses (bytes)
        uint32_t a_base[2], b_base[4];
#pragma unroll
        for (int mt = 0; mt < 2; mt++)
            a_base[mt] = smem_u32(ab + (warp_m * 32 + mt * 16 + a_row_l) * ASTRIDE + a_col16 * 4);
#pragma unroll
        for (int j = 0; j < 4; j++)
            b_base[j] = smem_u32(bb + (warp_n * 64 + j * 16 + b_row_l) * ASTRIDE + b_col16 * 4);

#pragma unroll
        for (int ks = 0; ks < 4; ks++) {               // 4 k-steps of 16 halves
            const uint32_t koff = ks * 32;             // bytes (8 uint32)
            uint32_t af[2][4];
#pragma unroll
            for (int mt = 0; mt < 2; mt++)
                LDSM4(af[mt][0], af[mt][1], af[mt][2], af[mt][3], a_base[mt] + koff);
            uint32_t bf[8][2];
#pragma unroll
            for (int j = 0; j < 4; j++)
                LDSM4(bf[2 * j][0], bf[2 * j][1], bf[2 * j + 1][0], bf[2 * j + 1][1],
                      b_base[j] + koff);
#pragma unroll
            for (int mt = 0; mt < 2; mt++)
#pragma unroll
                for (int nt = 0; nt < 8; nt++)
                    mma_f16(acc[mt][nt], af[mt], bf[nt]);
        }
        __syncthreads();
    }

    // epilogue: bias + convert to half (+ optional row sum-of-squares)
#pragma unroll
    for (int mt = 0; mt < 2; mt++) {
        const int r0 = rowBase + warp_m * 32 + mt * 16 + g;
        float ss0 = 0.f, ss1 = 0.f;
#pragma unroll
        for (int nt = 0; nt < 8; nt++) {
            const int c0 = colBase + warp_n * 64 + nt * 8 + 2 * t;
            float bx = 0.f, by = 0.f;
            if (bias) { bx = __ldg(&bias[c0]); by = __ldg(&bias[c0 + 1]); }
            float v0 = acc[mt][nt][0] + bx, v1 = acc[mt][nt][1] + by;
            float v2 = acc[mt][nt][2] + bx, v3 = acc[mt][nt][3] + by;
            if (NORM) { ss0 += v0 * v0 + v1 * v1; ss1 += v2 * v2 + v3 * v3; }
            if (r0 < M)
                *(__half2*)(C + (size_t)r0 * HID + c0) = __floats2half2_rn(v0, v1);
            if (r0 + 8 < M)
                *(__half2*)(C + (size_t)(r0 + 8) * HID + c0) = __floats2half2_rn(v2, v3);
        }
        if (NORM) {
            if (r0 < M) atomicAdd(&rowss[r0], ss0);
            if (r0 + 8 < M) atomicAdd(&rowss[r0 + 8], ss1);
        }
    }
}

// ---------------- weight transpose -> half: Wt[n][k] = half(W[k][n]) ----------------
__global__ void transpose_h_k(const float* __restrict__ W, __half* __restrict__ Wt, int K, int N) {
    __shared__ float t[32][33];
    const int l = blockIdx.z;
    const float* Wl = W + (size_t)l * K * N;
    __half* Wtl = Wt + (size_t)l * K * N;
    const int kb = blockIdx.x * 32, nb = blockIdx.y * 32;
    const int x = threadIdx.x, y = threadIdx.y;
#pragma unroll
    for (int i = y; i < 32; i += 8) t[i][x] = Wl[(size_t)(kb + i) * N + (nb + x)];
    __syncthreads();
#pragma unroll
    for (int i = y; i < 32; i += 8)
        Wtl[(size_t)(nb + i) * K + (kb + x)] = __float2half(t[x][i]);
}

// ---------------- fp32 -> fp16 convert ----------------
__global__ void f2h_k(const float* __restrict__ in, __half* __restrict__ out, int n2) {
    int i = blockIdx.x * blockDim.x + threadIdx.x;
    if (i >= n2) return;
    float2 v = ((const float2*)in)[i];
    ((__half2*)out)[i] = __floats2half2_rn(v.x, v.y);
}

// ---------------- zero / counts ----------------
__global__ void zero_f_k(float* __restrict__ p, int n) {
    int i = blockIdx.x * blockDim.x + threadIdx.x;
    if (i < n) p[i] = 0.f;
}
__global__ void zero_i_k(int* __restrict__ p, int n) {
    int i = blockIdx.x * blockDim.x + threadIdx.x;
    if (i < n) p[i] = 0;
}
__global__ void deg_k(const int* __restrict__ dst, int* __restrict__ deg, int E) {
    int i = blockIdx.x * blockDim.x + threadIdx.x;
    if (i < E) atomicAdd(&deg[dst[i]], 1);
}
__global__ void gcnt_k(const int* __restrict__ batch, int* __restrict__ c, int n) {
    int i = blockIdx.x * blockDim.x + threadIdx.x;
    if (i < n) atomicAdd(&c[batch[i]], 1);
}

// ---------------- CSR build ----------------
__global__ __launch_bounds__(1024) void scan_k(const int* __restrict__ deg,
                                               int* __restrict__ rowptr,
                                               int* __restrict__ cursor, int n) {
    __shared__ int part[1024];
    const int tid = threadIdx.x;
    const int per = (n + 1023) / 1024;
    const int start = tid * per;
    int s = 0;
    for (int i = 0; i < per; i++) {
        int idx = start + i;
        if (idx < n) s += deg[idx];
    }
    part[tid] = s;
    __syncthreads();
    for (int off = 1; off < 1024; off <<= 1) {
        int v = (tid >= off) ? part[tid - off] : 0;
        __syncthreads();
        part[tid] += v;
        __syncthreads();
    }
    int run = part[tid] - s;
    for (int i = 0; i < per; i++) {
        int idx = start + i;
        if (idx < n) {
            rowptr[idx] = run;
            cursor[idx] = run;
            run += deg[idx];
        }
    }
    if (tid == 1023) rowptr[n] = part[1023];
}

__global__ void fill_k(const int* __restrict__ src, const int* __restrict__ dst,
                       int* __restrict__ cursor, int* __restrict__ csr, int E) {
    int e = blockIdx.x * blockDim.x + threadIdx.x;
    if (e >= E) return;
    int d = dst[e];
    int p = atomicAdd(&cursor[d], 1);
    csr[p] = src[e];
}

// ---------------- CSR gather-mean aggregation (half in/out, fp32 accum) ----------------
__global__ __launch_bounds__(128) void agg_csr_h_k(const __half* __restrict__ h,
                                                   const int* __restrict__ csr,
                                                   const int* __restrict__ rowptr,
                                                   __half* __restrict__ aggr) {
    const int node = blockIdx.x;
    const int tid = threadIdx.x;          // owns 4 halves
    const int s = __ldg(&rowptr[node]);
    const int e = __ldg(&rowptr[node + 1]);
    float a0 = 0.f, a1 = 0.f, a2 = 0.f, a3 = 0.f;
    for (int i = s; i < e; i++) {
        int sr = __ldg(&csr[i]);
        uint2 v = __ldg((const uint2*)(h + (size_t)sr * HID) + tid);
        float2 f0 = __half22float2(*(__half2*)&v.x);
        float2 f1 = __half22float2(*(__half2*)&v.y);
        a0 += f0.x; a1 += f0.y; a2 += f1.x; a3 += f1.y;
    }
    float inv = 1.0f / fmaxf((float)(e - s), 1.0f);
    uint2 o;
    *(__half2*)&o.x = __floats2half2_rn(a0 * inv, a1 * inv);
    *(__half2*)&o.y = __floats2half2_rn(a2 * inv, a3 * inv);
    ((uint2*)(aggr + (size_t)node * HID))[tid] = o;
}

// ---------------- row-L2-normalize (norms precomputed) + BN column stats ----------------
__global__ __launch_bounds__(256) void rns_h_k(__half* __restrict__ X,
                                               const float* __restrict__ rowss,
                                               float* __restrict__ stats, int Nn) {
    __shared__ float invn[32];
    const int tid = threadIdx.x;
    const int row0 = blockIdx.x * 32;

    if (tid < 32) {
        int r = row0 + tid;
        float ss = (r < Nn) ? __ldg(&rowss[r]) : 1.f;
        invn[tid] = 1.0f / fmaxf(sqrtf(ss), 1e-12f);
    }
    __syncthreads();

    const int c0 = tid * 2;
    float s0 = 0.f, s1 = 0.f, q0 = 0.f, q1 = 0.f;
#pragma unroll 4
    for (int r = 0; r < 32; r++) {
        int rg = row0 + r;
        if (rg >= Nn) break;
        __half2* p = (__half2*)(X + (size_t)rg * HID + c0);
        float2 v = __half22float2(*p);
        float iv = invn[r];
        v.x *= iv; v.y *= iv;
        *p = __floats2half2_rn(v.x, v.y);
        s0 += v.x; s1 += v.y;
        q0 += v.x * v.x; q1 += v.y * v.y;
    }
    atomicAdd(&stats[c0], s0);
    atomicAdd(&stats[c0 + 1], s1);
    atomicAdd(&stats[HID + c0], q0);
    atomicAdd(&stats[HID + c0 + 1], q1);
}

// ---------------- BN apply + ReLU (half, in place) ----------------
__global__ void bn_apply_relu_h_k(__half* __restrict__ X, const float* __restrict__ stats,
                                  const float* __restrict__ gamma, const float* __restrict__ beta,
                                  float invN, int n2) {
    int i = blockIdx.x * blockDim.x + threadIdx.x;
    if (i >= n2) return;
    int c = (i & 255) * 2;
    float2 v = __half22float2(((const __half2*)X)[i]);
    float m0 = __ldg(&stats[c]) * invN, m1 = __ldg(&stats[c + 1]) * invN;
    float var0 = __ldg(&stats[HID + c]) * invN - m0 * m0;
    float var1 = __ldg(&stats[HID + c + 1]) * invN - m1 * m1;
    float y0 = (v.x - m0) * rsqrtf(var0 + EPSBN) * __ldg(&gamma[c]) + __ldg(&beta[c]);
    float y1 = (v.y - m1) * rsqrtf(var1 + EPSBN) * __ldg(&gamma[c + 1]) + __ldg(&beta[c + 1]);
    ((__half2*)X)[i] = __floats2half2_rn(fmaxf(y0, 0.f), fmaxf(y1, 0.f));
}

// ---------------- BN apply + ReLU + residual: h = relu(bn(u)) + h (half) ----------------
__global__ void bn_apply_relu_res_h_k(const __half* __restrict__ U, const float* __restrict__ stats,
                                      const float* __restrict__ gamma, const float* __restrict__ beta,
                                      __half* __restrict__ H, float invN, int n2) {
    int i = blockIdx.x * blockDim.x + threadIdx.x;
    if (i >= n2) return;
    int c = (i & 255) * 2;
    float2 v = __half22float2(((const __half2*)U)[i]);
    float2 a = __half22float2(((const __half2*)H)[i]);
    float m0 = __ldg(&stats[c]) * invN, m1 = __ldg(&stats[c + 1]) * invN;
    float var0 = __ldg(&stats[HID + c]) * invN - m0 * m0;
    float var1 = __ldg(&stats[HID + c + 1]) * invN - m1 * m1;
    float y0 = (v.x - m0) * rsqrtf(var0 + EPSBN) * __ldg(&gamma[c]) + __ldg(&beta[c]);
    float y1 = (v.y - m1) * rsqrtf(var1 + EPSBN) * __ldg(&gamma[c + 1]) + __ldg(&beta[c + 1]);
    ((__half2*)H)[i] = __floats2half2_rn(a.x + fmaxf(y0, 0.f), a.y + fmaxf(y1, 0.f));
}

// ---------------- attention + pool (half h, fp32 pool) ----------------
__global__ void att_pool_h_k(const __half* __restrict__ h, const float* __restrict__ Watt,
                             const int* __restrict__ batch, float* __restrict__ pool, int Nn) {
    int node = (blockIdx.x * blockDim.x + threadIdx.x) >> 5;
    int lane = threadIdx.x & 31;
    if (node >= Nn) return;
    const uint4* hr = (const uint4*)(h + (size_t)node * HID);
    float f[2][8];
    float dot = 0.f;
#pragma unroll
    for (int j = 0; j < 2; j++) {
        uint4 v = hr[lane + 32 * j];
        const uint32_t* u = (const uint32_t*)&v;
        int cb = (lane + 32 * j) * 8;
#pragma unroll
        for (int w = 0; w < 4; w++) {
            float2 p = __half22float2(*(__half2*)&u[w]);
            f[j][w * 2] = p.x; f[j][w * 2 + 1] = p.y;
            dot += p.x * __ldg(&Watt[cb + w * 2]) + p.y * __ldg(&Watt[cb + w * 2 + 1]);
        }
    }
#pragma unroll
    for (int off = 16; off > 0; off >>= 1)
        dot += __shfl_xor_sync(0xFFFFFFFFu, dot, off);
    float s = 1.0f / (1.0f + expf(-dot));
    float scale = (s + 1.0f) * 0.5f;
    int b = __ldg(&batch[node]);
    float* pr = pool + (size_t)b * HID;
#pragma unroll
    for (int j = 0; j < 2; j++) {
        int cb = (lane + 32 * j) * 8;
        red_add_v4((float4*)(pr + cb),
                   make_float4(f[j][0] * scale, f[j][1] * scale, f[j][2] * scale, f[j][3] * scale));
        red_add_v4((float4*)(pr + cb + 4),
                   make_float4(f[j][4] * scale, f[j][5] * scale, f[j][6] * scale, f[j][7] * scale));
    }
}

// ---------------- readout ----------------
__global__ void readout_k(const float* __restrict__ pool, const int* __restrict__ gcnt,
                          const float* __restrict__ Wr, float* __restrict__ out) {
    __shared__ float hrow[HID];
    int b = blockIdx.y;
    int n = blockIdx.x * blockDim.x + threadIdx.x;
    float invc = 1.0f / fmaxf((float)__ldg(&gcnt[b]), 1.0f);
    for (int i = threadIdx.x; i < HID; i += blockDim.x)
        hrow[i] = pool[(size_t)b * HID + i] * invc;
    __syncthreads();
    if (n >= NCLS) return;
    float acc = 0.f;
#pragma unroll 8
    for (int k = 0; k < HID; k++)
        acc += hrow[k] * __ldg(&Wr[(size_t)k * NCLS + n]);
    out[(size_t)b * NCLS + n] = acc;
}

// ---------------- host launcher ----------------
extern "C" void kernel_launch(void* const* d_in, const int* in_sizes, int n_in,
                              void* d_out, int out_size) {
    const float* x      = (const float*)d_in[0];
    const int*   ei     = (const int*)d_in[1];
    const int*   batch  = (const int*)d_in[2];
    const float* W_embed= (const float*)d_in[3];
    const float* W1     = (const float*)d_in[4];
    const float* b1     = (const float*)d_in[5];
    const float* g1     = (const float*)d_in[6];
    const float* be1    = (const float*)d_in[7];
    const float* W2     = (const float*)d_in[8];
    const float* b2     = (const float*)d_in[9];
    const float* g2     = (const float*)d_in[10];
    const float* be2    = (const float*)d_in[11];
    const float* W_att  = (const float*)d_in[12];
    const float* W_read = (const float*)d_in[13];
    float* out = (float*)d_out;

    const int Nn = in_sizes[2];
    const int E  = in_sizes[1] / 2;
    const int* src = ei;
    const int* dst = ei + E;

    __half *h, *ag, *t, *u, *xh, *w1t, *w2t, *wet;
    float *stats, *rowss, *pool;
    int *deg, *gcnt, *rowptr, *cursor, *csr;
    cudaGetSymbolAddress((void**)&h, g_h);
    cudaGetSymbolAddress((void**)&ag, g_aggr);
    cudaGetSymbolAddress((void**)&t, g_t);
    cudaGetSymbolAddress((void**)&u, g_u);
    cudaGetSymbolAddress((void**)&xh, g_xh);
    cudaGetSymbolAddress((void**)&stats, g_stats);
    cudaGetSymbolAddress((void**)&rowss, g_rowss);
    cudaGetSymbolAddress((void**)&pool, g_pool);
    cudaGetSymbolAddress((void**)&deg, g_deg);
    cudaGetSymbolAddress((void**)&gcnt, g_gcnt);
    cudaGetSymbolAddress((void**)&rowptr, g_rowptr);
    cudaGetSymbolAddress((void**)&cursor, g_cursor);
    cudaGetSymbolAddress((void**)&csr, g_csr);
    cudaGetSymbolAddress((void**)&w1t, g_w1t);
    cudaGetSymbolAddress((void**)&w2t, g_w2t);
    cudaGetSymbolAddress((void**)&wet, g_wet);

    static bool attr_set = false;
    if (!attr_set) {
        cudaFuncSetAttribute(gemm_h_k<false>, cudaFuncAttributeMaxDynamicSharedMemorySize, GEMM_SMEM);
        cudaFuncSetAttribute(gemm_h_k<true>, cudaFuncAttributeMaxDynamicSharedMemorySize, GEMM_SMEM);
        attr_set = true;
    }

    const int n2 = Nn * (HID / 2);
    const dim3 gemmGrid(HID / BN, (Nn + BM - 1) / BM);
    const float invN = 1.0f / (float)Nn;

    // launches 1-5: weight transpose -> half, x -> half, deg zero
    transpose_h_k<<<dim3(INDIM / 32, HID / 32, 1), dim3(32, 8)>>>(W_embed, wet, INDIM, HID);
    transpose_h_k<<<dim3(2 * HID / 32, HID / 32, LBLK), dim3(32, 8)>>>(W1, w1t, 2 * HID, HID);
    transpose_h_k<<<dim3(2 * HID / 32, HID / 32, LBLK), dim3(32, 8)>>>(W2, w2t, 2 * HID, HID);
    f2h_k<<<(Nn * INDIM / 2 + 255) / 256, 256>>>(x, xh, Nn * INDIM / 2);
    zero_i_k<<<(Nn + 255) / 256, 256>>>(deg, Nn);

    // launch 6 (ncu capture target): embed GEMM h = x @ W_embed
    gemm_h_k<false><<<gemmGrid, 256, GEMM_SMEM>>>(xh, INDIM, nullptr, 0, wet, nullptr, h, nullptr, Nn);

    // degree + CSR build
    deg_k<<<(E + 255) / 256, 256>>>(dst, deg, E);
    scan_k<<<1, 1024>>>(deg, rowptr, cursor, Nn);
    fill_k<<<(E + 255) / 256, 256>>>(src, dst, cursor, csr, E);

    for (int l = 0; l < 3; l++) {
        const __half* W1tl = w1t + (size_t)l * HID * 2 * HID;
        const float* b1l = b1 + l * HID;
        const float* g1l = g1 + l * HID;
        const float* be1l = be1 + l * HID;
        const __half* W2tl = w2t + (size_t)l * HID * 2 * HID;
        const float* b2l = b2 + l * HID;
        const float* g2l = g2 + l * HID;
        const float* be2l = be2 + l * HID;

        // ---- conv 1: h -> t ----
        agg_csr_h_k<<<Nn, 128>>>(h, csr, rowptr, ag);
        zero_f_k<<<(Nn + 255) / 256, 256>>>(rowss, Nn);
        zero_f_k<<<(2 * HID + 255) / 256, 256>>>(stats, 2 * HID);
        gemm_h_k<true><<<gemmGrid, 256, GEMM_SMEM>>>(h, HID, ag, HID, W1tl, b1l, t, rowss, Nn);
        rns_h_k<<<(Nn + 31) / 32, 256>>>(t, rowss, stats, Nn);
        bn_apply_relu_h_k<<<(n2 + 255) / 256, 256>>>(t, stats, g1l, be1l, invN, n2);

        // ---- conv 2: t -> u; h += relu(bn(u)) ----
        agg_csr_h_k<<<Nn, 128>>>(t, csr, rowptr, ag);
        zero_f_k<<<(Nn + 255) / 256, 256>>>(rowss, Nn);
        zero_f_k<<<(2 * HID + 255) / 256, 256>>>(stats, 2 * HID);
        gemm_h_k<true><<<gemmGrid, 256, GEMM_SMEM>>>(t, HID, ag, HID, W2tl, b2l, u, rowss, Nn);
        rns_h_k<<<(Nn + 31) / 32, 256>>>(u, rowss, stats, Nn);
        bn_apply_relu_res_h_k<<<(n2 + 255) / 256, 256>>>(u, stats, g2l, be2l, h, invN, n2);
    }

    // ---- attention + pool + readout ----
    zero_f_k<<<(BGRAPH * HID + 255) / 256, 256>>>(pool, BGRAPH * HID);
    zero_i_k<<<1, BGRAPH>>>(gcnt, BGRAPH);
    gcnt_k<<<(Nn + 255) / 256, 256>>>(batch, gcnt, Nn);
    att_pool_h_k<<<(Nn * 32 + 255) / 256, 256>>>(h, W_att, batch, pool, Nn);
    readout_k<<<dim3((NCLS + 255) / 256, BGRAPH), 256>>>(pool, gcnt, W_read, out);
}

// round 16
// speedup vs baseline: 1.0086x; 1.0086x over previous
#include <cuda_runtime.h>
#include <cuda_fp16.h>
#include <math.h>
#include <cstdint>

#define HID 512
#define NMAX 60000
#define EMAX 400000
#define BGRAPH 64
#define NCLS 1000
#define EPSBN 1e-5f
#define LBLK 3
#define INDIM 256

// ---------------- device scratch (fp16 activations, fp32 stats) ----------------
__device__ __half g_h[(size_t)NMAX * HID];
__device__ __half g_aggr[(size_t)NMAX * HID];
__device__ __half g_t[(size_t)NMAX * HID];
__device__ __half g_u[(size_t)NMAX * HID];
__device__ __half g_xh[(size_t)NMAX * INDIM];
__device__ int    g_deg[NMAX];
__device__ int    g_rowptr[NMAX + 1];
__device__ int    g_cursor[NMAX];
__device__ int    g_csr[EMAX];
__device__ float  g_stats[2 * HID];
__device__ float  g_rowss[NMAX];       // sum-of-squares from GEMM epilogue; colstats converts to inv-norm
__device__ float  g_pool[BGRAPH * HID];
__device__ int    g_gcnt[BGRAPH];
__device__ __half g_w1t[(size_t)LBLK * HID * 2 * HID];   // [L][512][1024] (N,K) half
__device__ __half g_w2t[(size_t)LBLK * HID * 2 * HID];
__device__ __half g_wet[(size_t)HID * INDIM];            // [512][256]

// ---------------- helpers ----------------
__device__ __forceinline__ uint32_t smem_u32(const void* p) {
    uint32_t a;
    asm("{ .reg .u64 t; cvta.to.shared.u64 t, %1; cvt.u32.u64 %0, t; }" : "=r"(a) : "l"(p));
    return a;
}
__device__ __forceinline__ void cp_async16(uint32_t saddr, const void* g) {
    asm volatile("cp.async.cg.shared.global [%0], [%1], 16;"
                 :: "r"(saddr), "l"(__cvta_generic_to_global((void*)g)) : "memory");
}
__device__ __forceinline__ void red_add_v4(float4* addr, float4 v) {
    asm volatile("red.global.add.v4.f32 [%0], {%1,%2,%3,%4};"
                 :: "l"(addr), "f"(v.x), "f"(v.y), "f"(v.z), "f"(v.w) : "memory");
}
__device__ __forceinline__ void mma_f16(float* c, const uint32_t* a, const uint32_t* b) {
    asm volatile(
        "mma.sync.aligned.m16n8k16.row.col.f32.f16.f16.f32 "
        "{%0,%1,%2,%3}, {%4,%5,%6,%7}, {%8,%9}, {%0,%1,%2,%3};"
        : "+f"(c[0]), "+f"(c[1]), "+f"(c[2]), "+f"(c[3])
        : "r"(a[0]), "r"(a[1]), "r"(a[2]), "r"(a[3]), "r"(b[0]), "r"(b[1]));
}
#define LDSM4(r0, r1, r2, r3, addr) \
    asm volatile("ldmatrix.sync.aligned.m8n8.x4.shared.b16 {%0,%1,%2,%3}, [%4];" \
                 : "=r"(r0), "=r"(r1), "=r"(r2), "=r"(r3) : "r"(addr))

// ---------------- fp16 tensor-core GEMM: C[M,512] = [A1|A2] @ Bt^T + bias ----------------
#define BM 128
#define BN 128
#define BKC 64
#define ASTRIDE 36
#define ASZ (128 * ASTRIDE)                 // uint32 per buffer
#define GEMM_SMEM (4 * ASZ * 4)             // bytes = 73728

template <bool NORM>
__global__ __launch_bounds__(256) void gemm_h_k(
    const __half* __restrict__ A1, int K1,
    const __half* __restrict__ A2, int K2,
    const __half* __restrict__ Bt,
    const float* __restrict__ bias,
    __half* __restrict__ C, float* __restrict__ rowss, int M)
{
    extern __shared__ uint32_t sm[];
    const int tid = threadIdx.x;
    const int wid = tid >> 5, lane = tid & 31;
    const int g = lane >> 2, t = lane & 3;
    const int warp_m = wid & 3, warp_n = wid >> 2;
    const int K = K1 + K2;
    const int nchunk = K / BKC;
    const int rowBase = blockIdx.y * BM;
    const int colBase = blockIdx.x * BN;

    const int quad = lane >> 3, qi = lane & 7;
    const int a_row_l = ((quad & 1) << 3) + qi;
    const int a_col16 = quad >> 1;
    const int b_row_l = ((quad >> 1) << 3) + qi;
    const int b_col16 = quad & 1;

    float acc[2][8][4];
#pragma unroll
    for (int mt = 0; mt < 2; mt++)
#pragma unroll
        for (int nt = 0; nt < 8; nt++)
#pragma unroll
            for (int q = 0; q < 4; q++) acc[mt][nt][q] = 0.f;

    auto load_chunk = [&](int ci, int b) {
        uint32_t* ab = sm + b * ASZ;
        uint32_t* bb = sm + 2 * ASZ + b * ASZ;
        const int k0 = ci * BKC;
#pragma unroll
        for (int j = 0; j < 4; j++) {
            int u = tid * 4 + j;
            int r = u >> 3, q = u & 7;
            uint32_t sa = smem_u32(ab + r * ASTRIDE + q * 4);
            int rg = rowBase + r;
            if (rg < M) {
                const __half* gp = (k0 < K1) ? (A1 + (size_t)rg * K1 + k0 + q * 8)
                                             : (A2 + (size_t)rg * K2 + (k0 - K1) + q * 8);
                cp_async16(sa, gp);
            } else {
                asm volatile("st.shared.v4.b32 [%0], {%1,%1,%1,%1};" :: "r"(sa), "r"(0) : "memory");
            }
        }
#pragma unroll
        for (int j = 0; j < 4; j++) {
            int u = tid * 4 + j;
            int r = u >> 3, q = u & 7;
            uint32_t sa = smem_u32(bb + r * ASTRIDE + q * 4);
            cp_async16(sa, Bt + (size_t)(colBase + r) * K + k0 + q * 8);
        }
        asm volatile("cp.async.commit_group;" ::: "memory");
    };

    load_chunk(0, 0);

    for (int ci = 0; ci < nchunk; ci++) {
        const int b = ci & 1;
        if (ci + 1 < nchunk) {
            load_chunk(ci + 1, b ^ 1);
            asm volatile("cp.async.wait_group 1;" ::: "memory");
        } else {
            asm volatile("cp.async.wait_group 0;" ::: "memory");
        }
        __syncthreads();

        uint32_t* ab = sm + b * ASZ;
        uint32_t* bb = sm + 2 * ASZ + b * ASZ;
        uint32_t a_base[2], b_base[4];
#pragma unroll
        for (int mt = 0; mt < 2; mt++)
            a_base[mt] = smem_u32(ab + (warp_m * 32 + mt * 16 + a_row_l) * ASTRIDE + a_col16 * 4);
#pragma unroll
        for (int j = 0; j < 4; j++)
            b_base[j] = smem_u32(bb + (warp_n * 64 + j * 16 + b_row_l) * ASTRIDE + b_col16 * 4);

#pragma unroll
        for (int ks = 0; ks < 4; ks++) {
            const uint32_t koff = ks * 32;
            uint32_t af[2][4];
#pragma unroll
            for (int mt = 0; mt < 2; mt++)
                LDSM4(af[mt][0], af[mt][1], af[mt][2], af[mt][3], a_base[mt] + koff);
            uint32_t bf[8][2];
#pragma unroll
            for (int j = 0; j < 4; j++)
                LDSM4(bf[2 * j][0], bf[2 * j][1], bf[2 * j + 1][0], bf[2 * j + 1][1],
                      b_base[j] + koff);
#pragma unroll
            for (int mt = 0; mt < 2; mt++)
#pragma unroll
                for (int nt = 0; nt < 8; nt++)
                    mma_f16(acc[mt][nt], af[mt], bf[nt]);
        }
        __syncthreads();
    }

#pragma unroll
    for (int mt = 0; mt < 2; mt++) {
        const int r0 = rowBase + warp_m * 32 + mt * 16 + g;
        float ss0 = 0.f, ss1 = 0.f;
#pragma unroll
        for (int nt = 0; nt < 8; nt++) {
            const int c0 = colBase + warp_n * 64 + nt * 8 + 2 * t;
            float bx = 0.f, by = 0.f;
            if (bias) { bx = __ldg(&bias[c0]); by = __ldg(&bias[c0 + 1]); }
            float v0 = acc[mt][nt][0] + bx, v1 = acc[mt][nt][1] + by;
            float v2 = acc[mt][nt][2] + bx, v3 = acc[mt][nt][3] + by;
            if (NORM) { ss0 += v0 * v0 + v1 * v1; ss1 += v2 * v2 + v3 * v3; }
            if (r0 < M)
                *(__half2*)(C + (size_t)r0 * HID + c0) = __floats2half2_rn(v0, v1);
            if (r0 + 8 < M)
                *(__half2*)(C + (size_t)(r0 + 8) * HID + c0) = __floats2half2_rn(v2, v3);
        }
        if (NORM) {
            if (r0 < M) atomicAdd(&rowss[r0], ss0);
            if (r0 + 8 < M) atomicAdd(&rowss[r0 + 8], ss1);
        }
    }
}

// ---------------- weight transpose -> half ----------------
__global__ void transpose_h_k(const float* __restrict__ W, __half* __restrict__ Wt, int K, int N) {
    __shared__ float t[32][33];
    const int l = blockIdx.z;
    const float* Wl = W + (size_t)l * K * N;
    __half* Wtl = Wt + (size_t)l * K * N;
    const int kb = blockIdx.x * 32, nb = blockIdx.y * 32;
    const int x = threadIdx.x, y = threadIdx.y;
#pragma unroll
    for (int i = y; i < 32; i += 8) t[i][x] = Wl[(size_t)(kb + i) * N + (nb + x)];
    __syncthreads();
#pragma unroll
    for (int i = y; i < 32; i += 8)
        Wtl[(size_t)(nb + i) * K + (kb + x)] = __float2half(t[x][i]);
}

// ---------------- fp32 -> fp16 convert ----------------
__global__ void f2h_k(const float* __restrict__ in, __half* __restrict__ out, int n2) {
    int i = blockIdx.x * blockDim.x + threadIdx.x;
    if (i >= n2) return;
    float2 v = ((const float2*)in)[i];
    ((__half2*)out)[i] = __floats2half2_rn(v.x, v.y);
}

// ---------------- zero / counts ----------------
__global__ void zero_f_k(float* __restrict__ p, int n) {
    int i = blockIdx.x * blockDim.x + threadIdx.x;
    if (i < n) p[i] = 0.f;
}
__global__ void zero_i_k(int* __restrict__ p, int n) {
    int i = blockIdx.x * blockDim.x + threadIdx.x;
    if (i < n) p[i] = 0;
}
// zero stats[0:1024) and rowss[0:Nn) in one launch
__global__ void zero2_k(float* __restrict__ stats, float* __restrict__ rowss, int Nn) {
    int i = blockIdx.x * blockDim.x + threadIdx.x;
    if (i < 2 * HID) stats[i] = 0.f;
    int j = i - 2 * HID;
    if (j >= 0 && j < Nn) rowss[j] = 0.f;
}
__global__ void deg_k(const int* __restrict__ dst, int* __restrict__ deg, int E) {
    int i = blockIdx.x * blockDim.x + threadIdx.x;
    if (i < E) atomicAdd(&deg[dst[i]], 1);
}
__global__ void gcnt_k(const int* __restrict__ batch, int* __restrict__ c, int n) {
    int i = blockIdx.x * blockDim.x + threadIdx.x;
    if (i < n) atomicAdd(&c[batch[i]], 1);
}

// ---------------- CSR build ----------------
__global__ __launch_bounds__(1024) void scan_k(const int* __restrict__ deg,
                                               int* __restrict__ rowptr,
                                               int* __restrict__ cursor, int n) {
    __shared__ int part[1024];
    const int tid = threadIdx.x;
    const int per = (n + 1023) / 1024;
    const int start = tid * per;
    int s = 0;
    for (int i = 0; i < per; i++) {
        int idx = start + i;
        if (idx < n) s += deg[idx];
    }
    part[tid] = s;
    __syncthreads();
    for (int off = 1; off < 1024; off <<= 1) {
        int v = (tid >= off) ? part[tid - off] : 0;
        __syncthreads();
        part[tid] += v;
        __syncthreads();
    }
    int run = part[tid] - s;
    for (int i = 0; i < per; i++) {
        int idx = start + i;
        if (idx < n) {
            rowptr[idx] = run;
            cursor[idx] = run;
            run += deg[idx];
        }
    }
    if (tid == 1023) rowptr[n] = part[1023];
}

__global__ void fill_k(const int* __restrict__ src, const int* __restrict__ dst,
                       int* __restrict__ cursor, int* __restrict__ csr, int E) {
    int e = blockIdx.x * blockDim.x + threadIdx.x;
    if (e >= E) return;
    int d = dst[e];
    int p = atomicAdd(&cursor[d], 1);
    csr[p] = src[e];
}

// ---------------- CSR gather-mean aggregation ----------------
__global__ __launch_bounds__(128) void agg_csr_h_k(const __half* __restrict__ h,
                                                   const int* __restrict__ csr,
                                                   const int* __restrict__ rowptr,
                                                   __half* __restrict__ aggr) {
    const int node = blockIdx.x;
    const int tid = threadIdx.x;
    const int s = __ldg(&rowptr[node]);
    const int e = __ldg(&rowptr[node + 1]);
    float a0 = 0.f, a1 = 0.f, a2 = 0.f, a3 = 0.f;
    for (int i = s; i < e; i++) {
        int sr = __ldg(&csr[i]);
        uint2 v = __ldg((const uint2*)(h + (size_t)sr * HID) + tid);
        float2 f0 = __half22float2(*(__half2*)&v.x);
        float2 f1 = __half22float2(*(__half2*)&v.y);
        a0 += f0.x; a1 += f0.y; a2 += f1.x; a3 += f1.y;
    }
    float inv = 1.0f / fmaxf((float)(e - s), 1.0f);
    uint2 o;
    *(__half2*)&o.x = __floats2half2_rn(a0 * inv, a1 * inv);
    *(__half2*)&o.y = __floats2half2_rn(a2 * inv, a3 * inv);
    ((uint2*)(aggr + (size_t)node * HID))[tid] = o;
}

// ---------------- column stats of row-normalized X (read-only); rowss -> inv-norm ----------------
__global__ __launch_bounds__(256) void colstats_h_k(const __half* __restrict__ X,
                                                    float* __restrict__ rowss,
                                                    float* __restrict__ stats, int Nn) {
    __shared__ float invn[32];
    const int tid = threadIdx.x;
    const int row0 = blockIdx.x * 32;

    if (tid < 32) {
        int r = row0 + tid;
        float inv = 1.f;
        if (r < Nn) {
            inv = 1.0f / fmaxf(sqrtf(__ldg(&rowss[r])), 1e-12f);
            rowss[r] = inv;     // cache inv-norm for the apply pass (this block owns these rows)
        }
        invn[tid] = inv;
    }
    __syncthreads();

    const int c0 = tid * 2;
    float s0 = 0.f, s1 = 0.f, q0 = 0.f, q1 = 0.f;
#pragma unroll 4
    for (int r = 0; r < 32; r++) {
        int rg = row0 + r;
        if (rg >= Nn) break;
        float2 v = __half22float2(*(const __half2*)(X + (size_t)rg * HID + c0));
        float iv = invn[r];
        v.x *= iv; v.y *= iv;
        s0 += v.x; s1 += v.y;
        q0 += v.x * v.x; q1 += v.y * v.y;
    }
    atomicAdd(&stats[c0], s0);
    atomicAdd(&stats[c0 + 1], s1);
    atomicAdd(&stats[HID + c0], q0);
    atomicAdd(&stats[HID + c0 + 1], q1);
}

// ---------------- fused normalize + BN + ReLU (in place): x = relu((x*inv - m)*rs*g + b) ----------------
__global__ void norm_bn_relu_h_k(__half* __restrict__ X, const float* __restrict__ rowinv,
                                 const float* __restrict__ stats,
                                 const float* __restrict__ gamma, const float* __restrict__ beta,
                                 float invN, int n2) {
    int i = blockIdx.x * blockDim.x + threadIdx.x;
    if (i >= n2) return;
    int c = (i & 255) * 2;
    int row = i >> 8;
    float iv = __ldg(&rowinv[row]);
    float2 v = __half22float2(((const __half2*)X)[i]);
    v.x *= iv; v.y *= iv;
    float m0 = __ldg(&stats[c]) * invN, m1 = __ldg(&stats[c + 1]) * invN;
    float var0 = __ldg(&stats[HID + c]) * invN - m0 * m0;
    float var1 = __ldg(&stats[HID + c + 1]) * invN - m1 * m1;
    float y0 = (v.x - m0) * rsqrtf(var0 + EPSBN) * __ldg(&gamma[c]) + __ldg(&beta[c]);
    float y1 = (v.y - m1) * rsqrtf(var1 + EPSBN) * __ldg(&gamma[c + 1]) + __ldg(&beta[c + 1]);
    ((__half2*)X)[i] = __floats2half2_rn(fmaxf(y0, 0.f), fmaxf(y1, 0.f));
}

// ---------------- fused normalize + BN + ReLU + residual: h += relu((u*inv - m)*rs*g + b) ----------------
__global__ void norm_bn_relu_res_h_k(const __half* __restrict__ U, const float* __restrict__ rowinv,
                                     const float* __restrict__ stats,
                                     const float* __restrict__ gamma, const float* __restrict__ beta,
                                     __half* __restrict__ H, float invN, int n2) {
    int i = blockIdx.x * blockDim.x + threadIdx.x;
    if (i >= n2) return;
    int c = (i & 255) * 2;
    int row = i >> 8;
    float iv = __ldg(&rowinv[row]);
    float2 v = __half22float2(((const __half2*)U)[i]);
    float2 a = __half22float2(((const __half2*)H)[i]);
    v.x *= iv; v.y *= iv;
    float m0 = __ldg(&stats[c]) * invN, m1 = __ldg(&stats[c + 1]) * invN;
    float var0 = __ldg(&stats[HID + c]) * invN - m0 * m0;
    float var1 = __ldg(&stats[HID + c + 1]) * invN - m1 * m1;
    float y0 = (v.x - m0) * rsqrtf(var0 + EPSBN) * __ldg(&gamma[c]) + __ldg(&beta[c]);
    float y1 = (v.y - m1) * rsqrtf(var1 + EPSBN) * __ldg(&gamma[c + 1]) + __ldg(&beta[c + 1]);
    ((__half2*)H)[i] = __floats2half2_rn(a.x + fmaxf(y0, 0.f), a.y + fmaxf(y1, 0.f));
}

// ---------------- attention + pool (half h, fp32 pool) ----------------
__global__ void att_pool_h_k(const __half* __restrict__ h, const float* __restrict__ Watt,
                             const int* __restrict__ batch, float* __restrict__ pool, int Nn) {
    int node = (blockIdx.x * blockDim.x + threadIdx.x) >> 5;
    int lane = threadIdx.x & 31;
    if (node >= Nn) return;
    const uint4* hr = (const uint4*)(h + (size_t)node * HID);
    float f[2][8];
    float dot = 0.f;
#pragma unroll
    for (int j = 0; j < 2; j++) {
        uint4 v = hr[lane + 32 * j];
        const uint32_t* u = (const uint32_t*)&v;
        int cb = (lane + 32 * j) * 8;
#pragma unroll
        for (int w = 0; w < 4; w++) {
            float2 p = __half22float2(*(__half2*)&u[w]);
            f[j][w * 2] = p.x; f[j][w * 2 + 1] = p.y;
            dot += p.x * __ldg(&Watt[cb + w * 2]) + p.y * __ldg(&Watt[cb + w * 2 + 1]);
        }
    }
#pragma unroll
    for (int off = 16; off > 0; off >>= 1)
        dot += __shfl_xor_sync(0xFFFFFFFFu, dot, off);
    float s = 1.0f / (1.0f + expf(-dot));
    float scale = (s + 1.0f) * 0.5f;
    int b = __ldg(&batch[node]);
    float* pr = pool + (size_t)b * HID;
#pragma unroll
    for (int j = 0; j < 2; j++) {
        int cb = (lane + 32 * j) * 8;
        red_add_v4((float4*)(pr + cb),
                   make_float4(f[j][0] * scale, f[j][1] * scale, f[j][2] * scale, f[j][3] * scale));
        red_add_v4((float4*)(pr + cb + 4),
                   make_float4(f[j][4] * scale, f[j][5] * scale, f[j][6] * scale, f[j][7] * scale));
    }
}

// ---------------- readout ----------------
__global__ void readout_k(const float* __restrict__ pool, const int* __restrict__ gcnt,
                          const float* __restrict__ Wr, float* __restrict__ out) {
    __shared__ float hrow[HID];
    int b = blockIdx.y;
    int n = blockIdx.x * blockDim.x + threadIdx.x;
    float invc = 1.0f / fmaxf((float)__ldg(&gcnt[b]), 1.0f);
    for (int i = threadIdx.x; i < HID; i += blockDim.x)
        hrow[i] = pool[(size_t)b * HID + i] * invc;
    __syncthreads();
    if (n >= NCLS) return;
    float acc = 0.f;
#pragma unroll 8
    for (int k = 0; k < HID; k++)
        acc += hrow[k] * __ldg(&Wr[(size_t)k * NCLS + n]);
    out[(size_t)b * NCLS + n] = acc;
}

// ---------------- host launcher ----------------
extern "C" void kernel_launch(void* const* d_in, const int* in_sizes, int n_in,
                              void* d_out, int out_size) {
    const float* x      = (const float*)d_in[0];
    const int*   ei     = (const int*)d_in[1];
    const int*   batch  = (const int*)d_in[2];
    const float* W_embed= (const float*)d_in[3];
    const float* W1     = (const float*)d_in[4];
    const float* b1     = (const float*)d_in[5];
    const float* g1     = (const float*)d_in[6];
    const float* be1    = (const float*)d_in[7];
    const float* W2     = (const float*)d_in[8];
    const float* b2     = (const float*)d_in[9];
    const float* g2     = (const float*)d_in[10];
    const float* be2    = (const float*)d_in[11];
    const float* W_att  = (const float*)d_in[12];
    const float* W_read = (const float*)d_in[13];
    float* out = (float*)d_out;

    const int Nn = in_sizes[2];
    const int E  = in_sizes[1] / 2;
    const int* src = ei;
    const int* dst = ei + E;

    __half *h, *ag, *t, *u, *xh, *w1t, *w2t, *wet;
    float *stats, *rowss, *pool;
    int *deg, *gcnt, *rowptr, *cursor, *csr;
    cudaGetSymbolAddress((void**)&h, g_h);
    cudaGetSymbolAddress((void**)&ag, g_aggr);
    cudaGetSymbolAddress((void**)&t, g_t);
    cudaGetSymbolAddress((void**)&u, g_u);
    cudaGetSymbolAddress((void**)&xh, g_xh);
    cudaGetSymbolAddress((void**)&stats, g_stats);
    cudaGetSymbolAddress((void**)&rowss, g_rowss);
    cudaGetSymbolAddress((void**)&pool, g_pool);
    cudaGetSymbolAddress((void**)&deg, g_deg);
    cudaGetSymbolAddress((void**)&gcnt, g_gcnt);
    cudaGetSymbolAddress((void**)&rowptr, g_rowptr);
    cudaGetSymbolAddress((void**)&cursor, g_cursor);
    cudaGetSymbolAddress((void**)&csr, g_csr);
    cudaGetSymbolAddress((void**)&w1t, g_w1t);
    cudaGetSymbolAddress((void**)&w2t, g_w2t);
    cudaGetSymbolAddress((void**)&wet, g_wet);

    static bool attr_set = false;
    if (!attr_set) {
        cudaFuncSetAttribute(gemm_h_k<false>, cudaFuncAttributeMaxDynamicSharedMemorySize, GEMM_SMEM);
        cudaFuncSetAttribute(gemm_h_k<true>, cudaFuncAttributeMaxDynamicSharedMemorySize, GEMM_SMEM);
        attr_set = true;
    }

    const int n2 = Nn * (HID / 2);
    const dim3 gemmGrid(HID / BN, (Nn + BM - 1) / BM);
    const float invN = 1.0f / (float)Nn;

    // launches 1-3, then GEMM as 4th (ncu capture target)
    f2h_k<<<(Nn * INDIM / 2 + 255) / 256, 256>>>(x, xh, Nn * INDIM / 2);
    transpose_h_k<<<dim3(INDIM / 32, HID / 32, 1), dim3(32, 8)>>>(W_embed, wet, INDIM, HID);
    transpose_h_k<<<dim3(2 * HID / 32, HID / 32, LBLK), dim3(32, 8)>>>(W1, w1t, 2 * HID, HID);
    gemm_h_k<false><<<gemmGrid, 256, GEMM_SMEM>>>(xh, INDIM, nullptr, 0, wet, nullptr, h, nullptr, Nn);

    // rest of prep
    transpose_h_k<<<dim3(2 * HID / 32, HID / 32, LBLK), dim3(32, 8)>>>(W2, w2t, 2 * HID, HID);
    zero_i_k<<<(Nn + 255) / 256, 256>>>(deg, Nn);
    deg_k<<<(E + 255) / 256, 256>>>(dst, deg, E);
    scan_k<<<1, 1024>>>(deg, rowptr, cursor, Nn);
    fill_k<<<(E + 255) / 256, 256>>>(src, dst, cursor, csr, E);

    const int z2blocks = (2 * HID + Nn + 255) / 256;

    for (int l = 0; l < 3; l++) {
        const __half* W1tl = w1t + (size_t)l * HID * 2 * HID;
        const float* b1l = b1 + l * HID;
        const float* g1l = g1 + l * HID;
        const float* be1l = be1 + l * HID;
        const __half* W2tl = w2t + (size_t)l * HID * 2 * HID;
        const float* b2l = b2 + l * HID;
        const float* g2l = g2 + l * HID;
        const float* be2l = be2 + l * HID;

        // ---- conv 1: h -> t ----
        agg_csr_h_k<<<Nn, 128>>>(h, csr, rowptr, ag);
        zero2_k<<<z2blocks, 256>>>(stats, rowss, Nn);
        gemm_h_k<true><<<gemmGrid, 256, GEMM_SMEM>>>(h, HID, ag, HID, W1tl, b1l, t, rowss, Nn);
        colstats_h_k<<<(Nn + 31) / 32, 256>>>(t, rowss, stats, Nn);
        norm_bn_relu_h_k<<<(n2 + 255) / 256, 256>>>(t, rowss, stats, g1l, be1l, invN, n2);

        // ---- conv 2: t -> u; h += relu(bn(norm(u))) ----
        agg_csr_h_k<<<Nn, 128>>>(t, csr, rowptr, ag);
        zero2_k<<<z2blocks, 256>>>(stats, rowss, Nn);
        gemm_h_k<true><<<gemmGrid, 256, GEMM_SMEM>>>(t, HID, ag, HID, W2tl, b2l, u, rowss, Nn);
        colstats_h_k<<<(Nn + 31) / 32, 256>>>(u, rowss, stats, Nn);
        norm_bn_relu_res_h_k<<<(n2 + 255) / 256, 256>>>(u, rowss, stats, g2l, be2l, h, invN, n2);
    }

    // ---- attention + pool + readout ----
    zero_f_k<<<(BGRAPH * HID + 255) / 256, 256>>>(pool, BGRAPH * HID);
    zero_i_k<<<1, BGRAPH>>>(gcnt, BGRAPH);
    gcnt_k<<<(Nn + 255) / 256, 256>>>(batch, gcnt, Nn);
    att_pool_h_k<<<(Nn * 32 + 255) / 256, 256>>>(h, W_att, batch, pool, Nn);
    readout_k<<<dim3((NCLS + 255) / 256, BGRAPH), 256>>>(pool, gcnt, W_read, out);
}

// round 17
// speedup vs baseline: 1.2013x; 1.1910x over previous
#include <cuda_runtime.h>
#include <cuda_fp16.h>
#include <math.h>
#include <cstdint>

#define HID 512
#define NMAX 60000
#define EMAX 400000
#define BGRAPH 64
#define NCLS 1000
#define EPSBN 1e-5f
#define LBLK 3
#define INDIM 256

// ---------------- device scratch (fp16 activations, fp32 stats) ----------------
__device__ __half g_h[(size_t)NMAX * HID];
__device__ __half g_aggr[(size_t)NMAX * HID];
__device__ __half g_t[(size_t)NMAX * HID];
__device__ __half g_u[(size_t)NMAX * HID];
__device__ __half g_xh[(size_t)NMAX * INDIM];
__device__ int    g_deg[NMAX];
__device__ int    g_rowptr[NMAX + 1];
__device__ int    g_cursor[NMAX];
__device__ int    g_csr[EMAX];
__device__ float  g_stats[2 * HID];
__device__ float  g_rowss[NMAX];       // sum-of-squares from GEMM epilogue; colstats converts to inv-norm
__device__ float  g_pool[BGRAPH * HID];
__device__ int    g_gcnt[BGRAPH];
__device__ __half g_w1t[(size_t)LBLK * HID * 2 * HID];   // [L][512][1024] (N,K) half
__device__ __half g_w2t[(size_t)LBLK * HID * 2 * HID];
__device__ __half g_wet[(size_t)HID * INDIM];            // [512][256]

// ---------------- helpers ----------------
__device__ __forceinline__ uint32_t smem_u32(const void* p) {
    uint32_t a;
    asm("{ .reg .u64 t; cvta.to.shared.u64 t, %1; cvt.u32.u64 %0, t; }" : "=r"(a) : "l"(p));
    return a;
}
__device__ __forceinline__ void cp_async16(uint32_t saddr, const void* g) {
    asm volatile("cp.async.cg.shared.global [%0], [%1], 16;"
                 :: "r"(saddr), "l"(__cvta_generic_to_global((void*)g)) : "memory");
}
__device__ __forceinline__ void red_add_v4(float4* addr, float4 v) {
    asm volatile("red.global.add.v4.f32 [%0], {%1,%2,%3,%4};"
                 :: "l"(addr), "f"(v.x), "f"(v.y), "f"(v.z), "f"(v.w) : "memory");
}
__device__ __forceinline__ void mma_f16(float* c, const uint32_t* a, const uint32_t* b) {
    asm volatile(
        "mma.sync.aligned.m16n8k16.row.col.f32.f16.f16.f32 "
        "{%0,%1,%2,%3}, {%4,%5,%6,%7}, {%8,%9}, {%0,%1,%2,%3};"
        : "+f"(c[0]), "+f"(c[1]), "+f"(c[2]), "+f"(c[3])
        : "r"(a[0]), "r"(a[1]), "r"(a[2]), "r"(a[3]), "r"(b[0]), "r"(b[1]));
}
#define LDSM4(r0, r1, r2, r3, addr) \
    asm volatile("ldmatrix.sync.aligned.m8n8.x4.shared.b16 {%0,%1,%2,%3}, [%4];" \
                 : "=r"(r0), "=r"(r1), "=r"(r2), "=r"(r3) : "r"(addr))

// ---------------- fp16 tensor-core GEMM: C[M,512] = [A1|A2] @ Bt^T + bias ----------------
#define BM 128
#define BN 128
#define BKC 64
#define ASTRIDE 36
#define ASZ (128 * ASTRIDE)                 // uint32 per buffer
#define GEMM_SMEM (4 * ASZ * 4)             // bytes = 73728

template <bool NORM>
__global__ __launch_bounds__(256, 2) void gemm_h_k(
    const __half* __restrict__ A1, int K1,
    const __half* __restrict__ A2, int K2,
    const __half* __restrict__ Bt,
    const float* __restrict__ bias,
    __half* __restrict__ C, float* __restrict__ rowss, int M)
{
    extern __shared__ uint32_t sm[];
    const int tid = threadIdx.x;
    const int wid = tid >> 5, lane = tid & 31;
    const int g = lane >> 2, t = lane & 3;
    const int warp_m = wid & 3, warp_n = wid >> 2;
    const int K = K1 + K2;
    const int nchunk = K / BKC;
    const int rowBase = blockIdx.y * BM;
    const int colBase = blockIdx.x * BN;

    const int quad = lane >> 3, qi = lane & 7;
    const int a_row_l = ((quad & 1) << 3) + qi;
    const int a_col16 = quad >> 1;
    const int b_row_l = ((quad >> 1) << 3) + qi;
    const int b_col16 = quad & 1;

    float acc[2][8][4];
#pragma unroll
    for (int mt = 0; mt < 2; mt++)
#pragma unroll
        for (int nt = 0; nt < 8; nt++)
#pragma unroll
            for (int q = 0; q < 4; q++) acc[mt][nt][q] = 0.f;

    auto load_chunk = [&](int ci, int b) {
        uint32_t* ab = sm + b * ASZ;
        uint32_t* bb = sm + 2 * ASZ + b * ASZ;
        const int k0 = ci * BKC;
#pragma unroll
        for (int j = 0; j < 4; j++) {
            int u = tid * 4 + j;
            int r = u >> 3, q = u & 7;
            uint32_t sa = smem_u32(ab + r * ASTRIDE + q * 4);
            int rg = rowBase + r;
            if (rg < M) {
                const __half* gp = (k0 < K1) ? (A1 + (size_t)rg * K1 + k0 + q * 8)
                                             : (A2 + (size_t)rg * K2 + (k0 - K1) + q * 8);
                cp_async16(sa, gp);
            } else {
                asm volatile("st.shared.v4.b32 [%0], {%1,%1,%1,%1};" :: "r"(sa), "r"(0) : "memory");
            }
        }
#pragma unroll
        for (int j = 0; j < 4; j++) {
            int u = tid * 4 + j;
            int r = u >> 3, q = u & 7;
            uint32_t sa = smem_u32(bb + r * ASTRIDE + q * 4);
            cp_async16(sa, Bt + (size_t)(colBase + r) * K + k0 + q * 8);
        }
        asm volatile("cp.async.commit_group;" ::: "memory");
    };

    load_chunk(0, 0);

    for (int ci = 0; ci < nchunk; ci++) {
        const int b = ci & 1;
        if (ci + 1 < nchunk) {
            load_chunk(ci + 1, b ^ 1);
            asm volatile("cp.async.wait_group 1;" ::: "memory");
        } else {
            asm volatile("cp.async.wait_group 0;" ::: "memory");
        }
        __syncthreads();

        uint32_t* ab = sm + b * ASZ;
        uint32_t* bb = sm + 2 * ASZ + b * ASZ;
        uint32_t a_base[2], b_base[4];
#pragma unroll
        for (int mt = 0; mt < 2; mt++)
            a_base[mt] = smem_u32(ab + (warp_m * 32 + mt * 16 + a_row_l) * ASTRIDE + a_col16 * 4);
#pragma unroll
        for (int j = 0; j < 4; j++)
            b_base[j] = smem_u32(bb + (warp_n * 64 + j * 16 + b_row_l) * ASTRIDE + b_col16 * 4);

#pragma unroll
        for (int ks = 0; ks < 4; ks++) {
            const uint32_t koff = ks * 32;
            uint32_t af[2][4];
#pragma unroll
            for (int mt = 0; mt < 2; mt++)
                LDSM4(af[mt][0], af[mt][1], af[mt][2], af[mt][3], a_base[mt] + koff);
            uint32_t bf[8][2];
#pragma unroll
            for (int j = 0; j < 4; j++)
                LDSM4(bf[2 * j][0], bf[2 * j][1], bf[2 * j + 1][0], bf[2 * j + 1][1],
                      b_base[j] + koff);
#pragma unroll
            for (int mt = 0; mt < 2; mt++)
#pragma unroll
                for (int nt = 0; nt < 8; nt++)
                    mma_f16(acc[mt][nt], af[mt], bf[nt]);
        }
        __syncthreads();
    }

#pragma unroll
    for (int mt = 0; mt < 2; mt++) {
        const int r0 = rowBase + warp_m * 32 + mt * 16 + g;
        float ss0 = 0.f, ss1 = 0.f;
#pragma unroll
        for (int nt = 0; nt < 8; nt++) {
            const int c0 = colBase + warp_n * 64 + nt * 8 + 2 * t;
            float bx = 0.f, by = 0.f;
            if (bias) { bx = __ldg(&bias[c0]); by = __ldg(&bias[c0 + 1]); }
            float v0 = acc[mt][nt][0] + bx, v1 = acc[mt][nt][1] + by;
            float v2 = acc[mt][nt][2] + bx, v3 = acc[mt][nt][3] + by;
            if (NORM) { ss0 += v0 * v0 + v1 * v1; ss1 += v2 * v2 + v3 * v3; }
            if (r0 < M)
                *(__half2*)(C + (size_t)r0 * HID + c0) = __floats2half2_rn(v0, v1);
            if (r0 + 8 < M)
                *(__half2*)(C + (size_t)(r0 + 8) * HID + c0) = __floats2half2_rn(v2, v3);
        }
        if (NORM) {
            if (r0 < M) atomicAdd(&rowss[r0], ss0);
            if (r0 + 8 < M) atomicAdd(&rowss[r0 + 8], ss1);
        }
    }
}

// ---------------- weight transpose -> half ----------------
__global__ void transpose_h_k(const float* __restrict__ W, __half* __restrict__ Wt, int K, int N) {
    __shared__ float t[32][33];
    const int l = blockIdx.z;
    const float* Wl = W + (size_t)l * K * N;
    __half* Wtl = Wt + (size_t)l * K * N;
    const int kb = blockIdx.x * 32, nb = blockIdx.y * 32;
    const int x = threadIdx.x, y = threadIdx.y;
#pragma unroll
    for (int i = y; i < 32; i += 8) t[i][x] = Wl[(size_t)(kb + i) * N + (nb + x)];
    __syncthreads();
#pragma unroll
    for (int i = y; i < 32; i += 8)
        Wtl[(size_t)(nb + i) * K + (kb + x)] = __float2half(t[x][i]);
}

// ---------------- fp32 -> fp16 convert ----------------
__global__ void f2h_k(const float* __restrict__ in, __half* __restrict__ out, int n2) {
    int i = blockIdx.x * blockDim.x + threadIdx.x;
    if (i >= n2) return;
    float2 v = ((const float2*)in)[i];
    ((__half2*)out)[i] = __floats2half2_rn(v.x, v.y);
}

// ---------------- zero / counts ----------------
__global__ void zero_f_k(float* __restrict__ p, int n) {
    int i = blockIdx.x * blockDim.x + threadIdx.x;
    if (i < n) p[i] = 0.f;
}
__global__ void zero_i_k(int* __restrict__ p, int n) {
    int i = blockIdx.x * blockDim.x + threadIdx.x;
    if (i < n) p[i] = 0;
}
// zero stats[0:1024) and rowss[0:Nn) in one launch
__global__ void zero2_k(float* __restrict__ stats, float* __restrict__ rowss, int Nn) {
    int i = blockIdx.x * blockDim.x + threadIdx.x;
    if (i < 2 * HID) stats[i] = 0.f;
    int j = i - 2 * HID;
    if (j >= 0 && j < Nn) rowss[j] = 0.f;
}
__global__ void deg_k(const int* __restrict__ dst, int* __restrict__ deg, int E) {
    int i = blockIdx.x * blockDim.x + threadIdx.x;
    if (i < E) atomicAdd(&deg[dst[i]], 1);
}
__global__ void gcnt_k(const int* __restrict__ batch, int* __restrict__ c, int n) {
    int i = blockIdx.x * blockDim.x + threadIdx.x;
    if (i < n) atomicAdd(&c[batch[i]], 1);
}

// ---------------- CSR build ----------------
__global__ __launch_bounds__(1024) void scan_k(const int* __restrict__ deg,
                                               int* __restrict__ rowptr,
                                               int* __restrict__ cursor, int n) {
    __shared__ int part[1024];
    const int tid = threadIdx.x;
    const int per = (n + 1023) / 1024;
    const int start = tid * per;
    int s = 0;
    for (int i = 0; i < per; i++) {
        int idx = start + i;
        if (idx < n) s += deg[idx];
    }
    part[tid] = s;
    __syncthreads();
    for (int off = 1; off < 1024; off <<= 1) {
        int v = (tid >= off) ? part[tid - off] : 0;
        __syncthreads();
        part[tid] += v;
        __syncthreads();
    }
    int run = part[tid] - s;
    for (int i = 0; i < per; i++) {
        int idx = start + i;
        if (idx < n) {
            rowptr[idx] = run;
            cursor[idx] = run;
            run += deg[idx];
        }
    }
    if (tid == 1023) rowptr[n] = part[1023];
}

__global__ void fill_k(const int* __restrict__ src, const int* __restrict__ dst,
                       int* __restrict__ cursor, int* __restrict__ csr, int E) {
    int e = blockIdx.x * blockDim.x + threadIdx.x;
    if (e >= E) return;
    int d = dst[e];
    int p = atomicAdd(&cursor[d], 1);
    csr[p] = src[e];
}

// ---------------- CSR gather-mean aggregation ----------------
__global__ __launch_bounds__(128) void agg_csr_h_k(const __half* __restrict__ h,
                                                   const int* __restrict__ csr,
                                                   const int* __restrict__ rowptr,
                                                   __half* __restrict__ aggr) {
    const int node = blockIdx.x;
    const int tid = threadIdx.x;
    const int s = __ldg(&rowptr[node]);
    const int e = __ldg(&rowptr[node + 1]);
    float a0 = 0.f, a1 = 0.f, a2 = 0.f, a3 = 0.f;
    for (int i = s; i < e; i++) {
        int sr = __ldg(&csr[i]);
        uint2 v = __ldg((const uint2*)(h + (size_t)sr * HID) + tid);
        float2 f0 = __half22float2(*(__half2*)&v.x);
        float2 f1 = __half22float2(*(__half2*)&v.y);
        a0 += f0.x; a1 += f0.y; a2 += f1.x; a3 += f1.y;
    }
    float inv = 1.0f / fmaxf((float)(e - s), 1.0f);
    uint2 o;
    *(__half2*)&o.x = __floats2half2_rn(a0 * inv, a1 * inv);
    *(__half2*)&o.y = __floats2half2_rn(a2 * inv, a3 * inv);
    ((uint2*)(aggr + (size_t)node * HID))[tid] = o;
}

// ---------------- column stats of row-normalized X (read-only); rowss -> inv-norm ----------------
__global__ __launch_bounds__(256) void colstats_h_k(const __half* __restrict__ X,
                                                    float* __restrict__ rowss,
                                                    float* __restrict__ stats, int Nn) {
    __shared__ float invn[32];
    const int tid = threadIdx.x;
    const int row0 = blockIdx.x * 32;

    if (tid < 32) {
        int r = row0 + tid;
        float inv = 1.f;
        if (r < Nn) {
            inv = 1.0f / fmaxf(sqrtf(__ldg(&rowss[r])), 1e-12f);
            rowss[r] = inv;     // cache inv-norm for the apply pass (this block owns these rows)
        }
        invn[tid] = inv;
    }
    __syncthreads();

    const int c0 = tid * 2;
    float s0 = 0.f, s1 = 0.f, q0 = 0.f, q1 = 0.f;
#pragma unroll 4
    for (int r = 0; r < 32; r++) {
        int rg = row0 + r;
        if (rg >= Nn) break;
        float2 v = __half22float2(*(const __half2*)(X + (size_t)rg * HID + c0));
        float iv = invn[r];
        v.x *= iv; v.y *= iv;
        s0 += v.x; s1 += v.y;
        q0 += v.x * v.x; q1 += v.y * v.y;
    }
    atomicAdd(&stats[c0], s0);
    atomicAdd(&stats[c0 + 1], s1);
    atomicAdd(&stats[HID + c0], q0);
    atomicAdd(&stats[HID + c0 + 1], q1);
}

// ---------------- fused normalize + BN + ReLU (in place) ----------------
__global__ void norm_bn_relu_h_k(__half* __restrict__ X, const float* __restrict__ rowinv,
                                 const float* __restrict__ stats,
                                 const float* __restrict__ gamma, const float* __restrict__ beta,
                                 float invN, int n2) {
    int i = blockIdx.x * blockDim.x + threadIdx.x;
    if (i >= n2) return;
    int c = (i & 255) * 2;
    int row = i >> 8;
    float iv = __ldg(&rowinv[row]);
    float2 v = __half22float2(((const __half2*)X)[i]);
    v.x *= iv; v.y *= iv;
    float m0 = __ldg(&stats[c]) * invN, m1 = __ldg(&stats[c + 1]) * invN;
    float var0 = __ldg(&stats[HID + c]) * invN - m0 * m0;
    float var1 = __ldg(&stats[HID + c + 1]) * invN - m1 * m1;
    float y0 = (v.x - m0) * rsqrtf(var0 + EPSBN) * __ldg(&gamma[c]) + __ldg(&beta[c]);
    float y1 = (v.y - m1) * rsqrtf(var1 + EPSBN) * __ldg(&gamma[c + 1]) + __ldg(&beta[c + 1]);
    ((__half2*)X)[i] = __floats2half2_rn(fmaxf(y0, 0.f), fmaxf(y1, 0.f));
}

// ---------------- fused normalize + BN + ReLU + residual ----------------
__global__ void norm_bn_relu_res_h_k(const __half* __restrict__ U, const float* __restrict__ rowinv,
                                     const float* __restrict__ stats,
                                     const float* __restrict__ gamma, const float* __restrict__ beta,
                                     __half* __restrict__ H, float invN, int n2) {
    int i = blockIdx.x * blockDim.x + threadIdx.x;
    if (i >= n2) return;
    int c = (i & 255) * 2;
    int row = i >> 8;
    float iv = __ldg(&rowinv[row]);
    float2 v = __half22float2(((const __half2*)U)[i]);
    float2 a = __half22float2(((const __half2*)H)[i]);
    v.x *= iv; v.y *= iv;
    float m0 = __ldg(&stats[c]) * invN, m1 = __ldg(&stats[c + 1]) * invN;
    float var0 = __ldg(&stats[HID + c]) * invN - m0 * m0;
    float var1 = __ldg(&stats[HID + c + 1]) * invN - m1 * m1;
    float y0 = (v.x - m0) * rsqrtf(var0 + EPSBN) * __ldg(&gamma[c]) + __ldg(&beta[c]);
    float y1 = (v.y - m1) * rsqrtf(var1 + EPSBN) * __ldg(&gamma[c + 1]) + __ldg(&beta[c + 1]);
    ((__half2*)H)[i] = __floats2half2_rn(a.x + fmaxf(y0, 0.f), a.y + fmaxf(y1, 0.f));
}

// ---------------- attention + pool (half h, fp32 pool) ----------------
__global__ void att_pool_h_k(const __half* __restrict__ h, const float* __restrict__ Watt,
                             const int* __restrict__ batch, float* __restrict__ pool, int Nn) {
    int node = (blockIdx.x * blockDim.x + threadIdx.x) >> 5;
    int lane = threadIdx.x & 31;
    if (node >= Nn) return;
    const uint4* hr = (const uint4*)(h + (size_t)node * HID);
    float f[2][8];
    float dot = 0.f;
#pragma unroll
    for (int j = 0; j < 2; j++) {
        uint4 v = hr[lane + 32 * j];
        const uint32_t* u = (const uint32_t*)&v;
        int cb = (lane + 32 * j) * 8;
#pragma unroll
        for (int w = 0; w < 4; w++) {
            float2 p = __half22float2(*(__half2*)&u[w]);
            f[j][w * 2] = p.x; f[j][w * 2 + 1] = p.y;
            dot += p.x * __ldg(&Watt[cb + w * 2]) + p.y * __ldg(&Watt[cb + w * 2 + 1]);
        }
    }
#pragma unroll
    for (int off = 16; off > 0; off >>= 1)
        dot += __shfl_xor_sync(0xFFFFFFFFu, dot, off);
    float s = 1.0f / (1.0f + expf(-dot));
    float scale = (s + 1.0f) * 0.5f;
    int b = __ldg(&batch[node]);
    float* pr = pool + (size_t)b * HID;
#pragma unroll
    for (int j = 0; j < 2; j++) {
        int cb = (lane + 32 * j) * 8;
        red_add_v4((float4*)(pr + cb),
                   make_float4(f[j][0] * scale, f[j][1] * scale, f[j][2] * scale, f[j][3] * scale));
        red_add_v4((float4*)(pr + cb + 4),
                   make_float4(f[j][4] * scale, f[j][5] * scale, f[j][6] * scale, f[j][7] * scale));
    }
}

// ---------------- readout ----------------
__global__ void readout_k(const float* __restrict__ pool, const int* __restrict__ gcnt,
                          const float* __restrict__ Wr, float* __restrict__ out) {
    __shared__ float hrow[HID];
    int b = blockIdx.y;
    int n = blockIdx.x * blockDim.x + threadIdx.x;
    float invc = 1.0f / fmaxf((float)__ldg(&gcnt[b]), 1.0f);
    for (int i = threadIdx.x; i < HID; i += blockDim.x)
        hrow[i] = pool[(size_t)b * HID + i] * invc;
    __syncthreads();
    if (n >= NCLS) return;
    float acc = 0.f;
#pragma unroll 8
    for (int k = 0; k < HID; k++)
        acc += hrow[k] * __ldg(&Wr[(size_t)k * NCLS + n]);
    out[(size_t)b * NCLS + n] = acc;
}

// ---------------- host launcher ----------------
extern "C" void kernel_launch(void* const* d_in, const int* in_sizes, int n_in,
                              void* d_out, int out_size) {
    const float* x      = (const float*)d_in[0];
    const int*   ei     = (const int*)d_in[1];
    const int*   batch  = (const int*)d_in[2];
    const float* W_embed= (const float*)d_in[3];
    const float* W1     = (const float*)d_in[4];
    const float* b1     = (const float*)d_in[5];
    const float* g1     = (const float*)d_in[6];
    const float* be1    = (const float*)d_in[7];
    const float* W2     = (const float*)d_in[8];
    const float* b2     = (const float*)d_in[9];
    const float* g2     = (const float*)d_in[10];
    const float* be2    = (const float*)d_in[11];
    const float* W_att  = (const float*)d_in[12];
    const float* W_read = (const float*)d_in[13];
    float* out = (float*)d_out;

    const int Nn = in_sizes[2];
    const int E  = in_sizes[1] / 2;
    const int* src = ei;
    const int* dst = ei + E;

    __half *h, *ag, *t, *u, *xh, *w1t, *w2t, *wet;
    float *stats, *rowss, *pool;
    int *deg, *gcnt, *rowptr, *cursor, *csr;
    cudaGetSymbolAddress((void**)&h, g_h);
    cudaGetSymbolAddress((void**)&ag, g_aggr);
    cudaGetSymbolAddress((void**)&t, g_t);
    cudaGetSymbolAddress((void**)&u, g_u);
    cudaGetSymbolAddress((void**)&xh, g_xh);
    cudaGetSymbolAddress((void**)&stats, g_stats);
    cudaGetSymbolAddress((void**)&rowss, g_rowss);
    cudaGetSymbolAddress((void**)&pool, g_pool);
    cudaGetSymbolAddress((void**)&deg, g_deg);
    cudaGetSymbolAddress((void**)&gcnt, g_gcnt);
    cudaGetSymbolAddress((void**)&rowptr, g_rowptr);
    cudaGetSymbolAddress((void**)&cursor, g_cursor);
    cudaGetSymbolAddress((void**)&csr, g_csr);
    cudaGetSymbolAddress((void**)&w1t, g_w1t);
    cudaGetSymbolAddress((void**)&w2t, g_w2t);
    cudaGetSymbolAddress((void**)&wet, g_wet);

    static bool attr_set = false;
    if (!attr_set) {
        cudaFuncSetAttribute(gemm_h_k<false>, cudaFuncAttributeMaxDynamicSharedMemorySize, GEMM_SMEM);
        cudaFuncSetAttribute(gemm_h_k<true>, cudaFuncAttributeMaxDynamicSharedMemorySize, GEMM_SMEM);
        attr_set = true;
    }

    const int n2 = Nn * (HID / 2);
    const dim3 gemmGrid(HID / BN, (Nn + BM - 1) / BM);
    const float invN = 1.0f / (float)Nn;

    // launches 1-3, then GEMM as 4th (ncu capture target)
    f2h_k<<<(Nn * INDIM / 2 + 255) / 256, 256>>>(x, xh, Nn * INDIM / 2);
    transpose_h_k<<<dim3(INDIM / 32, HID / 32, 1), dim3(32, 8)>>>(W_embed, wet, INDIM, HID);
    transpose_h_k<<<dim3(2 * HID / 32, HID / 32, LBLK), dim3(32, 8)>>>(W1, w1t, 2 * HID, HID);
    gemm_h_k<false><<<gemmGrid, 256, GEMM_SMEM>>>(xh, INDIM, nullptr, 0, wet, nullptr, h, nullptr, Nn);

    // rest of prep
    transpose_h_k<<<dim3(2 * HID / 32, HID / 32, LBLK), dim3(32, 8)>>>(W2, w2t, 2 * HID, HID);
    zero_i_k<<<(Nn + 255) / 256, 256>>>(deg, Nn);
    deg_k<<<(E + 255) / 256, 256>>>(dst, deg, E);
    scan_k<<<1, 1024>>>(deg, rowptr, cursor, Nn);
    fill_k<<<(E + 255) / 256, 256>>>(src, dst, cursor, csr, E);

    const int z2blocks = (2 * HID + Nn + 255) / 256;

    for (int l = 0; l < 3; l++) {
        const __half* W1tl = w1t + (size_t)l * HID * 2 * HID;
        const float* b1l = b1 + l * HID;
        const float* g1l = g1 + l * HID;
        const float* be1l = be1 + l * HID;
        const __half* W2tl = w2t + (size_t)l * HID * 2 * HID;
        const float* b2l = b2 + l * HID;
        const float* g2l = g2 + l * HID;
        const float* be2l = be2 + l * HID;

        // ---- conv 1: h -> t ----
        agg_csr_h_k<<<Nn, 128>>>(h, csr, rowptr, ag);
        zero2_k<<<z2blocks, 256>>>(stats, rowss, Nn);
        gemm_h_k<true><<<gemmGrid, 256, GEMM_SMEM>>>(h, HID, ag, HID, W1tl, b1l, t, rowss, Nn);
        colstats_h_k<<<(Nn + 31) / 32, 256>>>(t, rowss, stats, Nn);
        norm_bn_relu_h_k<<<(n2 + 255) / 256, 256>>>(t, rowss, stats, g1l, be1l, invN, n2);

        // ---- conv 2: t -> u; h += relu(bn(norm(u))) ----
        agg_csr_h_k<<<Nn, 128>>>(t, csr, rowptr, ag);
        zero2_k<<<z2blocks, 256>>>(stats, rowss, Nn);
        gemm_h_k<true><<<gemmGrid, 256, GEMM_SMEM>>>(t, HID, ag, HID, W2tl, b2l, u, rowss, Nn);
        colstats_h_k<<<(Nn + 31) / 32, 256>>>(u, rowss, stats, Nn);
        norm_bn_relu_res_h_k<<<(n2 + 255) / 256, 256>>>(u, rowss, stats, g2l, be2l, h, invN, n2);
    }

    // ---- attention + pool + readout ----
    zero_f_k<<<(BGRAPH * HID + 255) / 256, 256>>>(pool, BGRAPH * HID);
    zero_i_k<<<1, BGRAPH>>>(gcnt, BGRAPH);
    gcnt_k<<<(Nn + 255) / 256, 256>>>(batch, gcnt, Nn);
    att_pool_h_k<<<(Nn * 32 + 255) / 256, 256>>>(h, W_att, batch, pool, Nn);
    readout_k<<<dim3((NCLS + 255) / 256, BGRAPH), 256>>>(pool, gcnt, W_read, out);
}